// round 15
// baseline (speedup 1.0000x reference)
#include <cuda_runtime.h>
#include <math.h>

constexpr int DIM   = 192;
constexpr int SLICE = DIM * DIM;
constexpr int NVOX  = DIM * SLICE;

constexpr int OUT = 28;                      // output span per tile (32 - 2*2 halo)
constexpr int NB  = 7;
constexpr int CHZ = 16, NCH = DIM / CHZ;     // 12 z-chunks -> grid z = 48
constexpr int NIT = CHZ / 2 + 1;             // 9 double-plane steps
constexpr unsigned FULL = 0xffffffffu;

__device__ float  g_buf[2][4 * NVOX];
__device__ double g_acc[4];  // {sum(skelT*pred), sum(skelT), sum(skelP*target), sum(skelP)}

// MODE 0: raw inputs -> dst ; MODE 1: buf -> buf ; MODE 2: buf -> sums
// INT: block's 32x32 xy-footprint fully inside the volume.
template <int MODE, bool INT>
__device__ __forceinline__ void body(
    const float* __restrict__ src, float* __restrict__ dst,
    const float* __restrict__ other, int v, int zc,
    float2 (*xex)[2][16][16], float2 (*mex)[2][16][16])
{
    const int tx = threadIdx.x;            // 0..15, owns x = 2tx, 2tx+1
    const int ty = threadIdx.y;            // 0..15, owns y = 2ty, 2ty+1
    const int gx0 = blockIdx.x * OUT + 2 * tx - 2;
    const int gy0 = blockIdx.y * OUT + 2 * ty - 2;
    const float PINF = __int_as_float(0x7f800000);
    const float NINF = -PINF;

    bool gxin0 = true, gxin1 = true, gyin0 = true, gyin1 = true;
    if (!INT) {
        gxin0 = (unsigned)gx0 < (unsigned)DIM;
        gxin1 = (unsigned)(gx0 + 1) < (unsigned)DIM;
        gyin0 = (unsigned)gy0 < (unsigned)DIM;
        gyin1 = (unsigned)(gy0 + 1) < (unsigned)DIM;
    }
    const bool emit = (tx >= 1 && tx <= 14) && (ty >= 1 && ty <= 14);
    const bool colout0 = (tx >= 1 && tx <= 14) && gxin0;
    const bool colout1 = (tx >= 1 && tx <= 14) && gxin1;
    const bool rowout0 = (ty >= 1 && ty <= 14) && gyin0;
    const bool rowout1 = (ty >= 1 && ty <= 14) && gyin1;

    const int off00 = gy0 * DIM + gx0;

    auto loadP = [&](const float* sp, bool zin, float xv[2][2]) {
        if (INT) {
            if (zin) {
                float2 t0 = __ldg((const float2*)sp);
                float2 t1 = __ldg((const float2*)(sp + DIM));
                xv[0][0] = t0.x; xv[0][1] = t0.y;
                xv[1][0] = t1.x; xv[1][1] = t1.y;
            } else {
                xv[0][0] = xv[0][1] = xv[1][0] = xv[1][1] = PINF;
            }
        } else {
            #pragma unroll
            for (int j = 0; j < 2; ++j) {
                bool gj = (j == 0) ? gyin0 : gyin1;
                const float* rp = sp + j * DIM;
                if (zin && gj) {
                    if (gxin0 && gxin1) {
                        float2 t = __ldg((const float2*)rp);
                        xv[j][0] = t.x; xv[j][1] = t.y;
                    } else {
                        xv[j][0] = gxin0 ? __ldg(rp)     : PINF;
                        xv[j][1] = gxin1 ? __ldg(rp + 1) : PINF;
                    }
                } else {
                    xv[j][0] = PINF; xv[j][1] = PINF;
                }
            }
        }
    };
    auto pubX = [&](int s, const float xv[2][2]) {
        xex[s][0][ty][tx] = make_float2(xv[0][0], xv[0][1]);
        xex[s][1][ty][tx] = make_float2(xv[1][0], xv[1][1]);
    };
    auto pubM = [&](int s, const float mv[2][2]) {
        mex[s][0][ty][tx] = make_float2(mv[0][0], mv[0][1]);
        mex[s][1][ty][tx] = make_float2(mv[1][0], mv[1][1]);
    };
    // 7-pt min of plane z; y-halo via xex[slot]. No tx-edge fixups (tile-edge
    // columns lx {0,31} of M never reach emitted voxels lx 2..29).
    auto min7 = [&](const float xm[2][2], const float xq[2][2], const float xp[2][2],
                    int slot, bool pin, float mo[2][2]) {
        if (pin) {
            float2 yup = (ty > 0)  ? xex[slot][1][ty - 1][tx] : make_float2(PINF, PINF);
            float2 ydn = (ty < 15) ? xex[slot][0][ty + 1][tx] : make_float2(PINF, PINF);
            #pragma unroll
            for (int j = 0; j < 2; ++j) {
                float vL = __shfl_up_sync(FULL, xq[j][1], 1, 16);
                float vR = __shfl_down_sync(FULL, xq[j][0], 1, 16);
                float up0 = (j == 0) ? yup.x : xq[0][0];
                float up1 = (j == 0) ? yup.y : xq[0][1];
                float dn0 = (j == 1) ? ydn.x : xq[1][0];
                float dn1 = (j == 1) ? ydn.y : xq[1][1];
                float t  = fminf(xq[j][0], xq[j][1]);
                float a0 = fminf(fminf(t, vL), fminf(xm[j][0], xp[j][0]));
                a0 = fminf(a0, fminf(up0, dn0));
                float a1 = fminf(fminf(t, vR), fminf(xm[j][1], xp[j][1]));
                a1 = fminf(a1, fminf(up1, dn1));
                if (INT) {
                    mo[j][0] = a0; mo[j][1] = a1;
                } else {
                    bool gj = (j == 0) ? gyin0 : gyin1;
                    mo[j][0] = (gj && gxin0) ? a0 : NINF;
                    mo[j][1] = (gj && gxin1) ? a1 : NINF;
                }
            }
        } else {
            mo[0][0] = mo[0][1] = mo[1][0] = mo[1][1] = NINF;
        }
    };
    // 3x3 in-plane max of M; y-halo via mex[slot]. Same tile-edge argument.
    auto maxC2 = [&](const float mv[2][2], int slot, float co[2][2]) {
        float2 mup = (ty > 0)  ? mex[slot][1][ty - 1][tx] : make_float2(NINF, NINF);
        float2 mdn = (ty < 15) ? mex[slot][0][ty + 1][tx] : make_float2(NINF, NINF);
        float s0 = fmaxf(mv[0][0], mv[1][0]);
        float s1 = fmaxf(mv[0][1], mv[1][1]);
        float Vr[2][2];
        Vr[0][0] = fmaxf(mup.x, s0); Vr[0][1] = fmaxf(mup.y, s1);
        Vr[1][0] = fmaxf(s0, mdn.x); Vr[1][1] = fmaxf(s1, mdn.y);
        #pragma unroll
        for (int j = 0; j < 2; ++j) {
            float VL = __shfl_up_sync(FULL, Vr[j][1], 1, 16);
            float VR = __shfl_down_sync(FULL, Vr[j][0], 1, 16);
            float u = fmaxf(Vr[j][0], Vr[j][1]);
            co[j][0] = fmaxf(VL, u);
            co[j][1] = fmaxf(u, VR);
        }
    };

    float xA[2][2], xB[2][2], xC[2][2], xD[2][2], xE[2][2];
    float m0[2][2], m1[2][2], mP[2][2], ca[2][2], cb[2][2];

    // ---- prologue: x(zc-2..zc+1) resident; mP = M(zc-1); cb = C2(zc-1) ----
    {
        float xz2[2][2];
        const float* bp = src + off00;
        loadP(bp + (ptrdiff_t)(zc - 2) * SLICE, (unsigned)(zc - 2) < (unsigned)DIM, xz2);
        loadP(bp + (ptrdiff_t)(zc - 1) * SLICE, (unsigned)(zc - 1) < (unsigned)DIM, xA);
        loadP(bp + (ptrdiff_t)zc * SLICE,       true,                               xB);
        loadP(bp + (ptrdiff_t)(zc + 1) * SLICE, true,                               xC);
        pubX((zc - 2) & 3, xz2); pubX((zc - 1) & 3, xA);
        pubX(zc & 3, xB);        pubX((zc + 1) & 3, xC);
        __syncthreads();
        min7(xz2, xA, xB, (zc - 1) & 3, (unsigned)(zc - 1) < (unsigned)DIM, mP);
        pubM((zc - 1) & 3, mP);
        __syncthreads();
        maxC2(mP, (zc - 1) & 3, cb);
        #pragma unroll
        for (int j = 0; j < 2; ++j) { ca[j][0] = NINF; ca[j][1] = NINF; }
    }

    const float* ldc = src + off00 + (ptrdiff_t)(zc + 2) * SLICE;
    float*       stc = dst + off00 + (ptrdiff_t)(zc - 1) * SLICE;
    const float* otc = (MODE == 2) ? other + off00 + (ptrdiff_t)(zc - 1) * SLICE : nullptr;

    float accS = 0.0f, accP = 0.0f;

    // ---- main sweep: 9 double-plane steps, one barrier each; unroll 3 so the
    // register-plane rotation is renamed away inside each group ----
    #pragma unroll 3
    for (int it = 0; it < NIT; ++it) {
        const int p = zc + 2 * it;

        loadP(ldc,         p + 2 < DIM,                              xD);
        loadP(ldc + SLICE, (p + 3 < DIM) && (it + 1 < NIT),          xE);
        pubX((p + 2) & 3, xD);
        pubX((p + 3) & 3, xE);

        min7(xA, xB, xC, p & 3,       p < DIM,     m0);   // M(p)
        min7(xB, xC, xD, (p + 1) & 3, p + 1 < DIM, m1);   // M(p+1)
        pubM(p & 3, m0);
        pubM((p + 1) & 3, m1);
        __syncthreads();                                  // one barrier / 2 planes

        float cc0[2][2], cc1[2][2];
        maxC2(m0, p & 3, cc0);          // C2(p)
        maxC2(m1, (p + 1) & 3, cc1);    // C2(p+1)

        // emit q1 = p-1 : A=max(ca,cb,cc0), M=mP, x=xA
        if (it > 0) {
            float o[2][2];
            #pragma unroll
            for (int j = 0; j < 2; ++j)
                #pragma unroll
                for (int k = 0; k < 2; ++k) {
                    float A   = fmaxf(fmaxf(ca[j][k], cb[j][k]), cc0[j][k]);
                    float ctr = fmaxf(A - mP[j][k], 0.0f);
                    o[j][k]   = fmaxf(xA[j][k] - ctr, 0.0f);
                }
            if (INT) {
                if (MODE < 2) {
                    if (emit) {
                        *(float2*)stc         = make_float2(o[0][0], o[0][1]);
                        *(float2*)(stc + DIM) = make_float2(o[1][0], o[1][1]);
                    }
                } else if (emit) {
                    accS += (o[0][0] + o[0][1]) + (o[1][0] + o[1][1]);
                    accP += o[0][0] * __ldg(otc)       + o[0][1] * __ldg(otc + 1)
                          + o[1][0] * __ldg(otc + DIM) + o[1][1] * __ldg(otc + DIM + 1);
                }
            } else {
                #pragma unroll
                for (int j = 0; j < 2; ++j) {
                    bool rj = (j == 0) ? rowout0 : rowout1;
                    #pragma unroll
                    for (int k = 0; k < 2; ++k) {
                        bool ck = (k == 0) ? colout0 : colout1;
                        if (rj && ck) {
                            if (MODE < 2) stc[j * DIM + k] = o[j][k];
                            else {
                                float f = o[j][k];
                                accS += f;
                                accP += f * __ldg(otc + j * DIM + k);
                            }
                        }
                    }
                }
            }
        }
        // emit q2 = p : A=max(cb,cc0,cc1), M=m0, x=xB
        if (it < NIT - 1) {
            float o[2][2];
            #pragma unroll
            for (int j = 0; j < 2; ++j)
                #pragma unroll
                for (int k = 0; k < 2; ++k) {
                    float A   = fmaxf(fmaxf(cb[j][k], cc0[j][k]), cc1[j][k]);
                    float ctr = fmaxf(A - m0[j][k], 0.0f);
                    o[j][k]   = fmaxf(xB[j][k] - ctr, 0.0f);
                }
            if (INT) {
                if (MODE < 2) {
                    if (emit) {
                        *(float2*)(stc + SLICE)       = make_float2(o[0][0], o[0][1]);
                        *(float2*)(stc + SLICE + DIM) = make_float2(o[1][0], o[1][1]);
                    }
                } else if (emit) {
                    accS += (o[0][0] + o[0][1]) + (o[1][0] + o[1][1]);
                    accP += o[0][0] * __ldg(otc + SLICE)       + o[0][1] * __ldg(otc + SLICE + 1)
                          + o[1][0] * __ldg(otc + SLICE + DIM) + o[1][1] * __ldg(otc + SLICE + DIM + 1);
                }
            } else {
                #pragma unroll
                for (int j = 0; j < 2; ++j) {
                    bool rj = (j == 0) ? rowout0 : rowout1;
                    #pragma unroll
                    for (int k = 0; k < 2; ++k) {
                        bool ck = (k == 0) ? colout0 : colout1;
                        if (rj && ck) {
                            if (MODE < 2) stc[SLICE + j * DIM + k] = o[j][k];
                            else {
                                float f = o[j][k];
                                accS += f;
                                accP += f * __ldg(otc + SLICE + j * DIM + k);
                            }
                        }
                    }
                }
            }
        }

        // rotate (renamed away within unrolled groups)
        #pragma unroll
        for (int j = 0; j < 2; ++j)
            #pragma unroll
            for (int k = 0; k < 2; ++k) {
                xA[j][k] = xC[j][k]; xB[j][k] = xD[j][k]; xC[j][k] = xE[j][k];
                ca[j][k] = cc0[j][k]; cb[j][k] = cc1[j][k];
                mP[j][k] = m1[j][k];
            }
        ldc += 2 * SLICE;
        stc += 2 * SLICE;
        if (MODE == 2) otc += 2 * SLICE;
    }

    if (MODE == 2) {
        #pragma unroll
        for (int offm = 16; offm > 0; offm >>= 1) {
            accS += __shfl_down_sync(FULL, accS, offm);
            accP += __shfl_down_sync(FULL, accP, offm);
        }
        int lane = (tx + ty * 16) & 31;
        if (lane == 0) {
            if (v < 2) { atomicAdd(&g_acc[0], (double)accP); atomicAdd(&g_acc[1], (double)accS); }
            else       { atomicAdd(&g_acc[2], (double)accP); atomicAdd(&g_acc[3], (double)accS); }
        }
    }
}

template <int MODE>
__global__ __launch_bounds__(256, 4)
void fused_iter(int srcSel, int dstSel,
                const float* __restrict__ pred, const float* __restrict__ target) {
    __shared__ float2 xex[4][2][16][16];   // [slot][top/bot][ty][tx]
    __shared__ float2 mex[4][2][16][16];   // [slot][top/bot][ty][tx]

    const int v  = blockIdx.z / NCH;
    const int zc = (blockIdx.z % NCH) * CHZ;

    const float* src;
    if (MODE == 0) src = (v < 2) ? target + (size_t)v * NVOX
                                 : pred + (size_t)(v - 2) * NVOX;
    else           src = g_buf[srcSel] + (size_t)v * NVOX;
    float* dst = g_buf[dstSel] + (size_t)v * NVOX;
    const float* other = nullptr;
    if (MODE == 2) other = (v < 2) ? pred + (size_t)v * NVOX
                                   : target + (size_t)(v - 2) * NVOX;

    const bool interior = (blockIdx.x >= 1 && blockIdx.x <= 5 &&
                           blockIdx.y >= 1 && blockIdx.y <= 5);
    if (interior) body<MODE, true >(src, dst, other, v, zc, xex, mex);
    else          body<MODE, false>(src, dst, other, v, zc, xex, mex);
}

__global__ void zero_acc_kernel() {
    if (threadIdx.x < 4) g_acc[threadIdx.x] = 0.0;
}

__global__ void final_kernel(float* __restrict__ out) {
    double clrecall = (g_acc[0] + 1e-12) / (g_acc[1] + 1e-12);
    double clacc    = (g_acc[2] + 1e-12) / (g_acc[3] + 1e-12);
    double cldice   = 2.0 * clrecall * clacc / (clrecall + clacc);
    out[0] = (float)(1.0 - cldice);
}

extern "C" void kernel_launch(void* const* d_in, const int* in_sizes, int n_in,
                              void* d_out, int out_size) {
    const float* pred   = (const float*)d_in[0];
    const float* target = (const float*)d_in[1];
    float* out = (float*)d_out;

    dim3 blk(16, 16, 1);
    dim3 grd(NB, NB, 4 * NCH);

    zero_acc_kernel<<<1, 32>>>();
    fused_iter<0><<<grd, blk>>>(0, 0, pred, target);   // inputs -> buf0
    fused_iter<1><<<grd, blk>>>(0, 1, pred, target);   // buf0 -> buf1
    fused_iter<1><<<grd, blk>>>(1, 0, pred, target);   // buf1 -> buf0
    fused_iter<1><<<grd, blk>>>(0, 1, pred, target);   // buf0 -> buf1
    fused_iter<2><<<grd, blk>>>(1, 0, pred, target);   // buf1 -> sums
    final_kernel<<<1, 1>>>(out);
}

// round 16
// speedup vs baseline: 1.0117x; 1.0117x over previous
#include <cuda_runtime.h>
#include <math.h>

constexpr int DIM   = 192;
constexpr int SLICE = DIM * DIM;
constexpr int NVOX  = DIM * SLICE;

constexpr int OUT = 28;                      // output span per tile (32 - 2*2 halo)
constexpr int NB  = 7;
constexpr int CHZ = 32, NCH = DIM / CHZ;     // 6 z-chunks -> grid z = 24; 1176 blocks = 1.99 waves
constexpr unsigned FULL = 0xffffffffu;

__device__ float  g_buf[2][4 * NVOX];
__device__ double g_acc[4];  // {sum(skelT*pred), sum(skelT), sum(skelP*target), sum(skelP)}

// MODE 0: raw inputs -> dst ; MODE 1: buf -> buf ; MODE 2: buf -> sums
// INT: block's 32x32 xy-footprint fully inside the volume.
template <int MODE, bool INT>
__device__ __forceinline__ void body(
    const float* __restrict__ src, float* __restrict__ dst,
    const float* __restrict__ other, int v, int zc,
    float2 (*xex)[2][16][16], float2 (*mex)[2][16][16])
{
    const int tx = threadIdx.x;            // 0..15, owns x = 2tx, 2tx+1
    const int ty = threadIdx.y;            // 0..15, owns y = 2ty, 2ty+1
    const int gx0 = blockIdx.x * OUT + 2 * tx - 2;
    const int gy0 = blockIdx.y * OUT + 2 * ty - 2;
    const float PINF = __int_as_float(0x7f800000);
    const float NINF = -PINF;

    bool gxin0 = true, gxin1 = true, gyin0 = true, gyin1 = true;
    if (!INT) {
        gxin0 = (unsigned)gx0 < (unsigned)DIM;
        gxin1 = (unsigned)(gx0 + 1) < (unsigned)DIM;
        gyin0 = (unsigned)gy0 < (unsigned)DIM;
        gyin1 = (unsigned)(gy0 + 1) < (unsigned)DIM;
    }
    const bool emit = (tx >= 1 && tx <= 14) && (ty >= 1 && ty <= 14);
    const bool colout0 = (tx >= 1 && tx <= 14) && gxin0;
    const bool colout1 = (tx >= 1 && tx <= 14) && gxin1;
    const bool rowout0 = (ty >= 1 && ty <= 14) && gyin0;
    const bool rowout1 = (ty >= 1 && ty <= 14) && gyin1;

    const int off00 = gy0 * DIM + gx0;

    auto loadP = [&](const float* sp, bool zin, float xv[2][2]) {
        if (INT) {
            if (zin) {
                float2 t0 = __ldg((const float2*)sp);
                float2 t1 = __ldg((const float2*)(sp + DIM));
                xv[0][0] = t0.x; xv[0][1] = t0.y;
                xv[1][0] = t1.x; xv[1][1] = t1.y;
            } else {
                xv[0][0] = xv[0][1] = xv[1][0] = xv[1][1] = PINF;
            }
        } else {
            #pragma unroll
            for (int j = 0; j < 2; ++j) {
                bool gj = (j == 0) ? gyin0 : gyin1;
                const float* rp = sp + j * DIM;
                if (zin && gj) {
                    if (gxin0 && gxin1) {
                        float2 t = __ldg((const float2*)rp);
                        xv[j][0] = t.x; xv[j][1] = t.y;
                    } else {
                        xv[j][0] = gxin0 ? __ldg(rp)     : PINF;
                        xv[j][1] = gxin1 ? __ldg(rp + 1) : PINF;
                    }
                } else {
                    xv[j][0] = PINF; xv[j][1] = PINF;
                }
            }
        }
    };
    auto pubX = [&](int s, const float xv[2][2]) {
        xex[s][0][ty][tx] = make_float2(xv[0][0], xv[0][1]);
        xex[s][1][ty][tx] = make_float2(xv[1][0], xv[1][1]);
    };
    auto pubM = [&](int s, const float mv[2][2]) {
        mex[s][0][ty][tx] = make_float2(mv[0][0], mv[0][1]);
        mex[s][1][ty][tx] = make_float2(mv[1][0], mv[1][1]);
    };
    // 7-pt min of plane z; y-halo via xex[slot]. No tx-edge fixups (tile-edge
    // columns lx {0,31} of M never reach emitted voxels lx 2..29).
    auto min7 = [&](const float xm[2][2], const float xq[2][2], const float xp[2][2],
                    int slot, bool pin, float mo[2][2]) {
        if (pin) {
            float2 yup = (ty > 0)  ? xex[slot][1][ty - 1][tx] : make_float2(PINF, PINF);
            float2 ydn = (ty < 15) ? xex[slot][0][ty + 1][tx] : make_float2(PINF, PINF);
            #pragma unroll
            for (int j = 0; j < 2; ++j) {
                float vL = __shfl_up_sync(FULL, xq[j][1], 1, 16);
                float vR = __shfl_down_sync(FULL, xq[j][0], 1, 16);
                float up0 = (j == 0) ? yup.x : xq[0][0];
                float up1 = (j == 0) ? yup.y : xq[0][1];
                float dn0 = (j == 1) ? ydn.x : xq[1][0];
                float dn1 = (j == 1) ? ydn.y : xq[1][1];
                float t  = fminf(xq[j][0], xq[j][1]);
                float a0 = fminf(fminf(t, vL), fminf(xm[j][0], xp[j][0]));
                a0 = fminf(a0, fminf(up0, dn0));
                float a1 = fminf(fminf(t, vR), fminf(xm[j][1], xp[j][1]));
                a1 = fminf(a1, fminf(up1, dn1));
                if (INT) {
                    mo[j][0] = a0; mo[j][1] = a1;
                } else {
                    bool gj = (j == 0) ? gyin0 : gyin1;
                    mo[j][0] = (gj && gxin0) ? a0 : NINF;
                    mo[j][1] = (gj && gxin1) ? a1 : NINF;
                }
            }
        } else {
            mo[0][0] = mo[0][1] = mo[1][0] = mo[1][1] = NINF;
        }
    };
    // 3x3 in-plane max of M; y-halo via mex[slot]. Same tile-edge argument.
    auto maxC2 = [&](const float mv[2][2], int slot, float co[2][2]) {
        float2 mup = (ty > 0)  ? mex[slot][1][ty - 1][tx] : make_float2(NINF, NINF);
        float2 mdn = (ty < 15) ? mex[slot][0][ty + 1][tx] : make_float2(NINF, NINF);
        float s0 = fmaxf(mv[0][0], mv[1][0]);
        float s1 = fmaxf(mv[0][1], mv[1][1]);
        float Vr[2][2];
        Vr[0][0] = fmaxf(mup.x, s0); Vr[0][1] = fmaxf(mup.y, s1);
        Vr[1][0] = fmaxf(s0, mdn.x); Vr[1][1] = fmaxf(s1, mdn.y);
        #pragma unroll
        for (int j = 0; j < 2; ++j) {
            float VL = __shfl_up_sync(FULL, Vr[j][1], 1, 16);
            float VR = __shfl_down_sync(FULL, Vr[j][0], 1, 16);
            float u = fmaxf(Vr[j][0], Vr[j][1]);
            co[j][0] = fmaxf(VL, u);
            co[j][1] = fmaxf(u, VR);
        }
    };

    float xA[2][2], xB[2][2], xC[2][2], xD[2][2], xE[2][2];
    float m0[2][2], m1[2][2], mP[2][2], ca[2][2], cb[2][2];

    // ---- prologue: x(zc-2..zc+1) resident; mP = M(zc-1); cb = C2(zc-1) ----
    {
        float xz2[2][2];
        const float* bp = src + off00;
        loadP(bp + (ptrdiff_t)(zc - 2) * SLICE, (unsigned)(zc - 2) < (unsigned)DIM, xz2);
        loadP(bp + (ptrdiff_t)(zc - 1) * SLICE, (unsigned)(zc - 1) < (unsigned)DIM, xA);
        loadP(bp + (ptrdiff_t)zc * SLICE,       true,                               xB);
        loadP(bp + (ptrdiff_t)(zc + 1) * SLICE, true,                               xC);
        pubX((zc - 2) & 3, xz2); pubX((zc - 1) & 3, xA);
        pubX(zc & 3, xB);        pubX((zc + 1) & 3, xC);
        __syncthreads();
        min7(xz2, xA, xB, (zc - 1) & 3, (unsigned)(zc - 1) < (unsigned)DIM, mP);
        pubM((zc - 1) & 3, mP);
        __syncthreads();
        maxC2(mP, (zc - 1) & 3, cb);
        #pragma unroll
        for (int j = 0; j < 2; ++j) { ca[j][0] = NINF; ca[j][1] = NINF; }
    }

    const float* ldc = src + off00 + (ptrdiff_t)(zc + 2) * SLICE;
    float*       stc = dst + off00 + (ptrdiff_t)(zc - 1) * SLICE;
    const float* otc = (MODE == 2) ? other + off00 + (ptrdiff_t)(zc - 1) * SLICE : nullptr;

    float accS = 0.0f, accP = 0.0f;

    // ---- main sweep: two planes (p, p+1) per iteration, one barrier ----
    for (int p = zc; p <= zc + CHZ; p += 2) {
        loadP(ldc,         p + 2 < DIM,                              xD);
        loadP(ldc + SLICE, (p + 3 < DIM) && (p + 3 <= zc + CHZ + 1), xE);
        pubX((p + 2) & 3, xD);
        pubX((p + 3) & 3, xE);

        min7(xA, xB, xC, p & 3,       p < DIM,     m0);   // M(p)
        min7(xB, xC, xD, (p + 1) & 3, p + 1 < DIM, m1);   // M(p+1)
        pubM(p & 3, m0);
        pubM((p + 1) & 3, m1);
        __syncthreads();                                  // one barrier / 2 planes

        float cc0[2][2], cc1[2][2];
        maxC2(m0, p & 3, cc0);          // C2(p)
        maxC2(m1, (p + 1) & 3, cc1);    // C2(p+1)

        // emit q1 = p-1 : A=max(ca,cb,cc0), M=mP, x=xA
        if (p > zc) {
            float o[2][2];
            #pragma unroll
            for (int j = 0; j < 2; ++j)
                #pragma unroll
                for (int k = 0; k < 2; ++k) {
                    float A   = fmaxf(fmaxf(ca[j][k], cb[j][k]), cc0[j][k]);
                    float ctr = fmaxf(A - mP[j][k], 0.0f);
                    o[j][k]   = fmaxf(xA[j][k] - ctr, 0.0f);
                }
            if (INT) {
                if (MODE < 2) {
                    if (emit) {
                        *(float2*)stc         = make_float2(o[0][0], o[0][1]);
                        *(float2*)(stc + DIM) = make_float2(o[1][0], o[1][1]);
                    }
                } else if (emit) {
                    accS += (o[0][0] + o[0][1]) + (o[1][0] + o[1][1]);
                    accP += o[0][0] * __ldg(otc)       + o[0][1] * __ldg(otc + 1)
                          + o[1][0] * __ldg(otc + DIM) + o[1][1] * __ldg(otc + DIM + 1);
                }
            } else {
                #pragma unroll
                for (int j = 0; j < 2; ++j) {
                    bool rj = (j == 0) ? rowout0 : rowout1;
                    #pragma unroll
                    for (int k = 0; k < 2; ++k) {
                        bool ck = (k == 0) ? colout0 : colout1;
                        if (rj && ck) {
                            if (MODE < 2) stc[j * DIM + k] = o[j][k];
                            else {
                                float f = o[j][k];
                                accS += f;
                                accP += f * __ldg(otc + j * DIM + k);
                            }
                        }
                    }
                }
            }
        }
        // emit q2 = p : A=max(cb,cc0,cc1), M=m0, x=xB
        if (p < zc + CHZ) {
            float o[2][2];
            #pragma unroll
            for (int j = 0; j < 2; ++j)
                #pragma unroll
                for (int k = 0; k < 2; ++k) {
                    float A   = fmaxf(fmaxf(cb[j][k], cc0[j][k]), cc1[j][k]);
                    float ctr = fmaxf(A - m0[j][k], 0.0f);
                    o[j][k]   = fmaxf(xB[j][k] - ctr, 0.0f);
                }
            if (INT) {
                if (MODE < 2) {
                    if (emit) {
                        *(float2*)(stc + SLICE)       = make_float2(o[0][0], o[0][1]);
                        *(float2*)(stc + SLICE + DIM) = make_float2(o[1][0], o[1][1]);
                    }
                } else if (emit) {
                    accS += (o[0][0] + o[0][1]) + (o[1][0] + o[1][1]);
                    accP += o[0][0] * __ldg(otc + SLICE)       + o[0][1] * __ldg(otc + SLICE + 1)
                          + o[1][0] * __ldg(otc + SLICE + DIM) + o[1][1] * __ldg(otc + SLICE + DIM + 1);
                }
            } else {
                #pragma unroll
                for (int j = 0; j < 2; ++j) {
                    bool rj = (j == 0) ? rowout0 : rowout1;
                    #pragma unroll
                    for (int k = 0; k < 2; ++k) {
                        bool ck = (k == 0) ? colout0 : colout1;
                        if (rj && ck) {
                            if (MODE < 2) stc[SLICE + j * DIM + k] = o[j][k];
                            else {
                                float f = o[j][k];
                                accS += f;
                                accP += f * __ldg(otc + SLICE + j * DIM + k);
                            }
                        }
                    }
                }
            }
        }

        // rotate (shift by two planes)
        #pragma unroll
        for (int j = 0; j < 2; ++j)
            #pragma unroll
            for (int k = 0; k < 2; ++k) {
                xA[j][k] = xC[j][k]; xB[j][k] = xD[j][k]; xC[j][k] = xE[j][k];
                ca[j][k] = cc0[j][k]; cb[j][k] = cc1[j][k];
                mP[j][k] = m1[j][k];
            }
        ldc += 2 * SLICE;
        stc += 2 * SLICE;
        if (MODE == 2) otc += 2 * SLICE;
    }

    if (MODE == 2) {
        #pragma unroll
        for (int offm = 16; offm > 0; offm >>= 1) {
            accS += __shfl_down_sync(FULL, accS, offm);
            accP += __shfl_down_sync(FULL, accP, offm);
        }
        int lane = (tx + ty * 16) & 31;
        if (lane == 0) {
            if (v < 2) { atomicAdd(&g_acc[0], (double)accP); atomicAdd(&g_acc[1], (double)accS); }
            else       { atomicAdd(&g_acc[2], (double)accP); atomicAdd(&g_acc[3], (double)accS); }
        }
    }
}

template <int MODE>
__global__ __launch_bounds__(256, 4)
void fused_iter(int srcSel, int dstSel,
                const float* __restrict__ pred, const float* __restrict__ target) {
    __shared__ float2 xex[4][2][16][16];   // [slot][top/bot][ty][tx]
    __shared__ float2 mex[4][2][16][16];   // [slot][top/bot][ty][tx]

    const int v  = blockIdx.z / NCH;
    const int zc = (blockIdx.z % NCH) * CHZ;

    const float* src;
    if (MODE == 0) src = (v < 2) ? target + (size_t)v * NVOX
                                 : pred + (size_t)(v - 2) * NVOX;
    else           src = g_buf[srcSel] + (size_t)v * NVOX;
    float* dst = g_buf[dstSel] + (size_t)v * NVOX;
    const float* other = nullptr;
    if (MODE == 2) other = (v < 2) ? pred + (size_t)v * NVOX
                                   : target + (size_t)(v - 2) * NVOX;

    const bool interior = (blockIdx.x >= 1 && blockIdx.x <= 5 &&
                           blockIdx.y >= 1 && blockIdx.y <= 5);
    if (interior) body<MODE, true >(src, dst, other, v, zc, xex, mex);
    else          body<MODE, false>(src, dst, other, v, zc, xex, mex);
}

__global__ void zero_acc_kernel() {
    if (threadIdx.x < 4) g_acc[threadIdx.x] = 0.0;
}

__global__ void final_kernel(float* __restrict__ out) {
    double clrecall = (g_acc[0] + 1e-12) / (g_acc[1] + 1e-12);
    double clacc    = (g_acc[2] + 1e-12) / (g_acc[3] + 1e-12);
    double cldice   = 2.0 * clrecall * clacc / (clrecall + clacc);
    out[0] = (float)(1.0 - cldice);
}

extern "C" void kernel_launch(void* const* d_in, const int* in_sizes, int n_in,
                              void* d_out, int out_size) {
    const float* pred   = (const float*)d_in[0];
    const float* target = (const float*)d_in[1];
    float* out = (float*)d_out;

    dim3 blk(16, 16, 1);
    dim3 grd(NB, NB, 4 * NCH);

    zero_acc_kernel<<<1, 32>>>();
    fused_iter<0><<<grd, blk>>>(0, 0, pred, target);   // inputs -> buf0
    fused_iter<1><<<grd, blk>>>(0, 1, pred, target);   // buf0 -> buf1
    fused_iter<1><<<grd, blk>>>(1, 0, pred, target);   // buf1 -> buf0
    fused_iter<1><<<grd, blk>>>(0, 1, pred, target);   // buf0 -> buf1
    fused_iter<2><<<grd, blk>>>(1, 0, pred, target);   // buf1 -> sums
    final_kernel<<<1, 1>>>(out);
}